// round 7
// baseline (speedup 1.0000x reference)
#include <cuda_runtime.h>
#include <cstdint>
#include <cstddef>

#define T_STEPS 2048
#define B_SIZE  256
#define I_SIZE  64
#define H_SIZE  128

// Scratch: precomputed input projections x@Wi + bi, layout [T][B][3*H]
// (gate-major within last dim: [r | z | n]).  805 MB static device array.
__device__ float g_xproj[(size_t)T_STEPS * B_SIZE * 3 * H_SIZE];

__device__ __forceinline__ float sigmoidf_(float x) {
    return 1.0f / (1.0f + __expf(-x));
}
// Safe fast tanh: correct limits at +/-inf (no NaN), abs err ~1e-7.
__device__ __forceinline__ float tanhf_(float x) {
    return 1.0f - 2.0f / (1.0f + __expf(2.0f * x));
}

// ============================================================================
// Phase 1: xproj[t,b, g*128 + j] = sum_i x[t,b,i] * Wg[i,j] + bg[j]
// Tiled SIMT GEMM: block tile = 64 rows (flattened t*B+b) x 128 cols (one gate)
// grid = (TB/64, 3), 256 threads, each thread computes a 4x8 register tile.
// ============================================================================
__global__ __launch_bounds__(256, 2) void xproj_kernel(
    const float* __restrict__ x,
    const float* __restrict__ Wir, const float* __restrict__ Wiz, const float* __restrict__ Win,
    const float* __restrict__ bir, const float* __restrict__ biz, const float* __restrict__ bin_)
{
    __shared__ float xs[I_SIZE][68];        // x tile transposed: xs[i][row], padded
    __shared__ float ws[I_SIZE][H_SIZE];    // weight tile: ws[k][j]
    __shared__ float bs[H_SIZE];

    const int g = blockIdx.y;
    const float* __restrict__ W    = (g == 0) ? Wir : (g == 1) ? Wiz : Win;
    const float* __restrict__ bias = (g == 0) ? bir : (g == 1) ? biz : bin_;

    const int tid = threadIdx.x;
    const size_t r_base = (size_t)blockIdx.x * 64;

    // Load x tile [64 rows x 64 cols], store transposed into SMEM.
    const float* __restrict__ xg = x + r_base * I_SIZE;
    #pragma unroll
    for (int s = 0; s < 16; s++) {
        int idx = tid + 256 * s;            // 0..4095
        int row = idx >> 6;
        int i   = idx & 63;
        xs[i][row] = xg[idx];
    }
    // Load W [64 x 128] (same layout as global).
    #pragma unroll
    for (int s = 0; s < 32; s++) {
        int idx = tid + 256 * s;            // 0..8191
        ((float*)ws)[idx] = W[idx];
    }
    if (tid < H_SIZE) bs[tid] = bias[tid];
    __syncthreads();

    const int tr = tid & 15;                // 16 thread-rows
    const int tc = tid >> 4;                // 16 thread-cols
    const int r0 = tr * 4;
    const int c0 = tc * 8;

    float acc[4][8];
    #pragma unroll
    for (int r = 0; r < 4; r++)
        #pragma unroll
        for (int c = 0; c < 8; c++)
            acc[r][c] = 0.0f;

    #pragma unroll 8
    for (int k = 0; k < I_SIZE; k++) {
        float4 xa  = *(const float4*)&xs[k][r0];
        float4 wb0 = *(const float4*)&ws[k][c0];
        float4 wb1 = *(const float4*)&ws[k][c0 + 4];
        float xr[4] = {xa.x, xa.y, xa.z, xa.w};
        float wc8[8] = {wb0.x, wb0.y, wb0.z, wb0.w, wb1.x, wb1.y, wb1.z, wb1.w};
        #pragma unroll
        for (int r = 0; r < 4; r++)
            #pragma unroll
            for (int c = 0; c < 8; c++)
                acc[r][c] = fmaf(xr[r], wc8[c], acc[r][c]);
    }

    // Store: out row = r_base + r0 + r, cols g*128 + c0 .. +7 (float4 aligned).
    #pragma unroll
    for (int r = 0; r < 4; r++) {
        size_t row = r_base + (size_t)(r0 + r);
        float* op = g_xproj + row * (3 * H_SIZE) + g * H_SIZE + c0;
        float4 o0, o1;
        o0.x = acc[r][0] + bs[c0 + 0];
        o0.y = acc[r][1] + bs[c0 + 1];
        o0.z = acc[r][2] + bs[c0 + 2];
        o0.w = acc[r][3] + bs[c0 + 3];
        o1.x = acc[r][4] + bs[c0 + 4];
        o1.y = acc[r][5] + bs[c0 + 5];
        o1.z = acc[r][6] + bs[c0 + 6];
        o1.w = acc[r][7] + bs[c0 + 7];
        *(float4*)(op)     = o0;
        *(float4*)(op + 4) = o1;
    }
}

// ============================================================================
// Phase 2: persistent per-batch GRU recurrence + fused classifier.
// grid = 128 blocks (2 batch rows each), 384 threads.
// thread = (gate g in {r,z,n}, hidden col j). Wh column lives in registers.
// ============================================================================
__global__ __launch_bounds__(384, 1) void gru_kernel(
    const float* __restrict__ Whr, const float* __restrict__ Whz, const float* __restrict__ Whn,
    const float* __restrict__ bhn, const float* __restrict__ Wc,  const float* __restrict__ bc,
    float* __restrict__ out)
{
    __shared__ float h_s[2][H_SIZE];
    __shared__ float r_s[2][H_SIZE];
    __shared__ float z_s[2][H_SIZE];
    __shared__ float cls[2][4];

    const int tid = threadIdx.x;
    const int g   = tid >> 7;       // 0=r, 1=z, 2=n
    const int j   = tid & 127;
    const int b0  = blockIdx.x * 2;

    const float* __restrict__ Wh = (g == 0) ? Whr : (g == 1) ? Whz : Whn;

    // Register-resident weight column: w[k] = Wh[k][j]
    float w[H_SIZE];
    #pragma unroll
    for (int k = 0; k < H_SIZE; k++) w[k] = Wh[k * H_SIZE + j];

    const float bhn_j = bhn[j];
    const float wc_j  = Wc[j];
    const float bc0   = bc[0];

    if (tid < 2 * H_SIZE) ((float*)h_s)[tid] = 0.0f;   // h0 = 0
    __syncthreads();

    const float* __restrict__ xp = g_xproj + (size_t)b0 * (3 * H_SIZE) + g * H_SIZE + j;
    const size_t step_stride = (size_t)B_SIZE * 3 * H_SIZE;

    for (int t = 0; t < T_STEPS; t++) {
        // Prefetch input projections early (independent of the matmul).
        const float* xpt = xp + (size_t)t * step_stride;
        float x0 = xpt[0];
        float x1 = xpt[3 * H_SIZE];

        // acc[row] = sum_k h[row][k] * Wh[k][j]
        float a0 = 0.f, a1 = 0.f, a2 = 0.f, a3 = 0.f;
        float d0 = 0.f, d1 = 0.f, d2 = 0.f, d3 = 0.f;
        #pragma unroll
        for (int k4 = 0; k4 < H_SIZE / 4; k4++) {
            float4 h0 = *(const float4*)&h_s[0][k4 * 4];
            float4 h1 = *(const float4*)&h_s[1][k4 * 4];
            a0 = fmaf(h0.x, w[4 * k4 + 0], a0);
            a1 = fmaf(h0.y, w[4 * k4 + 1], a1);
            a2 = fmaf(h0.z, w[4 * k4 + 2], a2);
            a3 = fmaf(h0.w, w[4 * k4 + 3], a3);
            d0 = fmaf(h1.x, w[4 * k4 + 0], d0);
            d1 = fmaf(h1.y, w[4 * k4 + 1], d1);
            d2 = fmaf(h1.z, w[4 * k4 + 2], d2);
            d3 = fmaf(h1.w, w[4 * k4 + 3], d3);
        }
        float acc0 = (a0 + a1) + (a2 + a3);
        float acc1 = (d0 + d1) + (d2 + d3);

        if (g == 0) {
            r_s[0][j] = sigmoidf_(x0 + acc0);
            r_s[1][j] = sigmoidf_(x1 + acc1);
        } else if (g == 1) {
            z_s[0][j] = sigmoidf_(x0 + acc0);
            z_s[1][j] = sigmoidf_(x1 + acc1);
        }
        __syncthreads();   // r,z ready

        if (g == 2) {
            float h0o = h_s[0][j];
            float h1o = h_s[1][j];
            float n0 = tanhf_(x0 + r_s[0][j] * (acc0 + bhn_j));
            float n1 = tanhf_(x1 + r_s[1][j] * (acc1 + bhn_j));
            float z0 = z_s[0][j];
            float z1 = z_s[1][j];
            float hn0 = (1.0f - z0) * n0 + z0 * h0o;
            float hn1 = (1.0f - z1) * n1 + z1 * h1o;
            h_s[0][j] = hn0;
            h_s[1][j] = hn1;

            // Fused classifier partial: dot(h_new, Wc) via warp reduction.
            float v0 = hn0 * wc_j;
            float v1 = hn1 * wc_j;
            #pragma unroll
            for (int off = 16; off > 0; off >>= 1) {
                v0 += __shfl_down_sync(0xffffffffu, v0, off);
                v1 += __shfl_down_sync(0xffffffffu, v1, off);
            }
            int w4 = (tid >> 5) & 3;   // warp index within gate-2 group
            if ((tid & 31) == 0) { cls[0][w4] = v0; cls[1][w4] = v1; }
        }
        __syncthreads();   // h_new + cls ready

        if (tid < 2) {
            float s = ((cls[tid][0] + cls[tid][1]) + (cls[tid][2] + cls[tid][3])) + bc0;
            out[(size_t)t * B_SIZE + b0 + tid] = sigmoidf_(s);
        }
        // cls is safely re-read before gate-2 warps can rewrite it: the rewrite
        // happens after the NEXT iteration's first __syncthreads, which requires
        // tid<2 (gate-0 threads) to have arrived, i.e. after their read.
    }
}

// ============================================================================
extern "C" void kernel_launch(void* const* d_in, const int* in_sizes, int n_in,
                              void* d_out, int out_size)
{
    const float* x    = (const float*)d_in[0];
    const float* Wir  = (const float*)d_in[1];
    const float* Wiz  = (const float*)d_in[2];
    const float* Win  = (const float*)d_in[3];
    const float* bir  = (const float*)d_in[4];
    const float* biz  = (const float*)d_in[5];
    const float* bin_ = (const float*)d_in[6];
    const float* Whr  = (const float*)d_in[7];
    const float* Whz  = (const float*)d_in[8];
    const float* Whn  = (const float*)d_in[9];
    const float* bhn  = (const float*)d_in[10];
    const float* Wc   = (const float*)d_in[11];
    const float* bc   = (const float*)d_in[12];
    float* out = (float*)d_out;

    // Phase 1: input projections (fully parallel over T*B).
    dim3 grid1((T_STEPS * B_SIZE) / 64, 3);
    xproj_kernel<<<grid1, 256>>>(x, Wir, Wiz, Win, bir, biz, bin_);

    // Phase 2: sequential recurrence, batch-parallel across 128 blocks.
    gru_kernel<<<B_SIZE / 2, 384>>>(Whr, Whz, Whn, bhn, Wc, bc, out);
}